// round 13
// baseline (speedup 1.0000x reference)
#include <cuda_runtime.h>
#include <cuda_fp16.h>
#include <math.h>
#include <stdint.h>
#include <string.h>

// ---------------------------------------------------------------------------
// Problem constants: B=2, S=2048, D=1024, H=16, head_dim=64, rope dims=32
// ---------------------------------------------------------------------------
#define BV 2
#define HV 16
#define SV 2048
#define DV 1024
#define KD 64
#define MROWS (BV*SV)        // 4096
#define HEADROWS (BV*HV*SV)  // 65536

// Scratch (device globals: allocation-free rule)
__device__ float g_rope[SV * 16 * 2];     // (sin, cos) per (s, pair)
__device__ __half g_xh[MROWS * DV];
__device__ __half g_wh[4 * DV * DV];
__device__ __half g_qh[HEADROWS * KD];
__device__ __half g_kh[HEADROWS * KD];
__device__ __half g_vh[HEADROWS * KD];
__device__ __half g_yh[MROWS * DV];

// ---------------------------------------------------------------------------
// helpers
// ---------------------------------------------------------------------------
__device__ __forceinline__ uint32_t smem_u32(const void* p) {
    uint32_t a;
    asm("{ .reg .u64 t; cvta.to.shared.u64 t, %1; cvt.u32.u64 %0, t; }"
        : "=r"(a) : "l"(p));
    return a;
}

#define SWZ(o) ((o) ^ (((o) >> 3) & 0x70))

__device__ __forceinline__ void ldm4(uint32_t* r, uint32_t addr) {
    asm volatile("ldmatrix.sync.aligned.m8n8.x4.shared.b16 {%0,%1,%2,%3}, [%4];"
                 : "=r"(r[0]), "=r"(r[1]), "=r"(r[2]), "=r"(r[3]) : "r"(addr));
}

__device__ __forceinline__ void ldm4t(uint32_t* r, uint32_t addr) {
    asm volatile("ldmatrix.sync.aligned.m8n8.x4.trans.shared.b16 {%0,%1,%2,%3}, [%4];"
                 : "=r"(r[0]), "=r"(r[1]), "=r"(r[2]), "=r"(r[3]) : "r"(addr));
}

// f32-accumulate fp16 mma
__device__ __forceinline__ void mma_f32(float* c, const uint32_t* a,
                                        uint32_t b0, uint32_t b1) {
    asm volatile(
        "mma.sync.aligned.m16n8k16.row.col.f32.f16.f16.f32 "
        "{%0,%1,%2,%3},{%4,%5,%6,%7},{%8,%9},{%0,%1,%2,%3};"
        : "+f"(c[0]), "+f"(c[1]), "+f"(c[2]), "+f"(c[3])
        : "r"(a[0]), "r"(a[1]), "r"(a[2]), "r"(a[3]), "r"(b0), "r"(b1));
}

__device__ __forceinline__ void cp16(uint32_t saddr, const void* gaddr) {
    asm volatile("cp.async.cg.shared.global [%0], [%1], 16;"
                 :: "r"(saddr), "l"(gaddr) : "memory");
}
#define CP_COMMIT() asm volatile("cp.async.commit_group;" ::: "memory")
#define CP_WAIT1()  asm volatile("cp.async.wait_group 1;" ::: "memory")
#define CP_WAIT0()  asm volatile("cp.async.wait_group 0;" ::: "memory")

__device__ __forceinline__ uint32_t b2u(__half2 v) {
    uint32_t u;
    memcpy(&u, &v, 4);
    return u;
}

// ---------------------------------------------------------------------------
// Fused prelude: one launch, region-decoded grid.
//   blocks [0,4096)      : x fp32 -> fp16
//   blocks [4096,8192)   : weight transpose + scale + fp16 (4 weights)
//   blocks [8192,8320)   : RoPE sin/cos table
// ---------------------------------------------------------------------------
#define NB_TOHALF 4096
#define NB_TRANS  4096
#define NB_ROPE   128

__global__ __launch_bounds__(256)
void prelude_kernel(const float* __restrict__ x,
                    const float* __restrict__ W0, const float* __restrict__ W1,
                    const float* __restrict__ W2, const float* __restrict__ W3,
                    __half* __restrict__ xh, __half* __restrict__ wh_all,
                    float* __restrict__ tbl) {
    const int bid = blockIdx.x;
    const int t = threadIdx.x;
    __shared__ float tile[32][33];

    if (bid < NB_TOHALF) {
        int i = bid * 256 + t;
        float4 v = ((const float4*)x)[i];
        *(__half2*)(xh + 4 * i)     = __floats2half2_rn(v.x, v.y);
        *(__half2*)(xh + 4 * i + 2) = __floats2half2_rn(v.z, v.w);
        return;
    }
    if (bid < NB_TOHALF + NB_TRANS) {
        int r = bid - NB_TOHALF;
        int widx = r >> 10;
        int rr = r & 1023;
        int bx = (rr & 31) * 32, by = (rr >> 5) * 32;
        const float* Ws[4] = { W0, W1, W2, W3 };
        const float* W = Ws[widx];
        const float scale = (widx == 0) ? 0.125f : 1.0f;
        __half* hi = wh_all + (size_t)widx * DV * DV;
        int tx = t & 31, ty = t >> 5;
#pragma unroll
        for (int q = 0; q < 32; q += 8)
            tile[ty + q][tx] = W[(size_t)(by + ty + q) * DV + bx + tx];
        __syncthreads();
#pragma unroll
        for (int q = 0; q < 32; q += 8)
            hi[(size_t)(bx + ty + q) * DV + by + tx] =
                __float2half_rn(tile[tx][ty + q] * scale);
        return;
    }
    {
        int idx = (bid - NB_TOHALF - NB_TRANS) * 256 + t;
        int i = idx & 15, s = idx >> 4;
        float inv = powf(10000.0f, -(float)i / 16.0f);
        float sn, cs;
        sincosf((float)s * inv, &sn, &cs);
        tbl[2 * idx]     = sn;
        tbl[2 * idx + 1] = cs;
    }
}

// ---------------------------------------------------------------------------
// fp16 GEMM (f32 accumulate): C = Ah @ Bh^T.   (round-9 proven config)
// 128x128 block tile, BK=64, 3-stage cp.async pipeline, 512 threads
// (16 warps, 4x4, 32x32 warp tile).
// MODE 0: plain fp32 C output.
// MODE 1: fused QKV epilogue — RoPE + fp16 convert + head-major repack.
// ---------------------------------------------------------------------------
#define GBM 128
#define GBN 128
#define GBK 64
#define TILE_BYTES (GBM * GBK * 2)
#define STAGE_BYTES (2 * TILE_BYTES)      // Ah, Bh
#define NSTAGE 3
#define GEMM_SMEM (NSTAGE * STAGE_BYTES)  // 98304
#define NITER (DV / GBK)                  // 16

__device__ __forceinline__ void qkv_store(
    int r, int c, float v0, float v1, const float* __restrict__ tbl,
    __half* __restrict__ qh, __half* __restrict__ kh, __half* __restrict__ vh) {
    const int b = r >> 11, s = r & (SV - 1);
    const int tt = c >> 10;              // 0=q, 1=k, 2=v
    const int cd = c & (DV - 1);
    const int h = cd >> 6, d = cd & (KD - 1);
    if (tt < 2 && d < 32) {
        float2 sc = *(const float2*)(tbl + (size_t)(s * 16 + (d >> 1)) * 2);
        float a = v0 * sc.y - v1 * sc.x;
        float bq = v1 * sc.y + v0 * sc.x;
        v0 = a; v1 = bq;
    }
    const size_t o = (((size_t)(b * HV + h)) * SV + s) * KD + d;
    __half* dst = (tt == 0) ? qh : (tt == 1) ? kh : vh;
    *(__half2*)(dst + o) = __floats2half2_rn(v0, v1);
}

template <int MODE>
__global__ __launch_bounds__(512, 1)
void mma_gemm(const __half* __restrict__ Ah,
              const __half* __restrict__ Bh,
              float* __restrict__ C, int ldc,
              const float* __restrict__ tbl,
              __half* __restrict__ qh, __half* __restrict__ kh,
              __half* __restrict__ vh) {
    extern __shared__ __align__(1024) char sm[];
    const uint32_t sb = smem_u32(sm);
    const int t = threadIdx.x;
    const int lane = t & 31, wid = t >> 5;
    const int warpM = wid & 3, warpN = wid >> 2;
    const int row0 = blockIdx.y * GBM;
    const int col0 = blockIdx.x * GBN;

    const __half* srcs[2] = { Ah + (size_t)row0 * DV, Bh + (size_t)col0 * DV };

    const int cm = t >> 3;        // 0..63
    const int cc = t & 7;

    float accF[2][4][4];
#pragma unroll
    for (int i = 0; i < 2; i++)
#pragma unroll
        for (int j = 0; j < 4; j++)
#pragma unroll
            for (int r = 0; r < 4; r++) accF[i][j][r] = 0.0f;

    const int sub = lane >> 3, l7 = lane & 7;
    const int rowA0 = warpM * 32 + ((sub & 1) << 3) + l7;
    const int rowA1 = rowA0 + 16;
    const int kA = (sub >> 1);
    int rowB[2];
#pragma unroll
    for (int p = 0; p < 2; p++)
        rowB[p] = warpN * 32 + p * 16 + ((sub >> 1) << 3) + l7;
    const int kB = (sub & 1);

    auto issue = [&](int st) {
        const int k0 = st * GBK;
        const uint32_t stb = sb + (st % NSTAGE) * STAGE_BYTES;
#pragma unroll
        for (int tile = 0; tile < 2; tile++) {
#pragma unroll
            for (int j = 0; j < 2; j++) {
                int m = cm + 64 * j;
                cp16(stb + tile * TILE_BYTES + SWZ(m * 128 + cc * 16),
                     srcs[tile] + (size_t)m * DV + k0 + cc * 8);
            }
        }
        CP_COMMIT();
    };

    issue(0);
    issue(1);

    for (int it = 0; it < NITER; it++) {
        if (it == NITER - 1) { CP_WAIT0(); } else { CP_WAIT1(); }
        __syncthreads();
        if (it + 2 < NITER) issue(it + 2);

        const uint32_t ahB = sb + (it % NSTAGE) * STAGE_BYTES;
        const uint32_t bhB = ahB + TILE_BYTES;

#pragma unroll
        for (int ks = 0; ks < 4; ks++) {
            const int kcA = ks * 2 + kA;
            const int kcB = ks * 2 + kB;
            uint32_t ah[2][4];
            ldm4(ah[0], ahB + SWZ(rowA0 * 128 + kcA * 16));
            ldm4(ah[1], ahB + SWZ(rowA1 * 128 + kcA * 16));
            uint32_t bh[2][4];
#pragma unroll
            for (int p = 0; p < 2; p++)
                ldm4(bh[p], bhB + SWZ(rowB[p] * 128 + kcB * 16));
#pragma unroll
            for (int mt = 0; mt < 2; mt++) {
#pragma unroll
                for (int nt = 0; nt < 4; nt++) {
                    const int p = nt >> 1, o = (nt & 1) * 2;
                    mma_f32(accF[mt][nt], ah[mt], bh[p][o], bh[p][o + 1]);
                }
            }
        }
    }

#pragma unroll
    for (int mt = 0; mt < 2; mt++) {
#pragma unroll
        for (int nt = 0; nt < 4; nt++) {
            float v0 = accF[mt][nt][0], v1 = accF[mt][nt][1];
            float v2 = accF[mt][nt][2], v3 = accF[mt][nt][3];
            int r = row0 + warpM * 32 + mt * 16 + (lane >> 2);
            int c = col0 + warpN * 32 + nt * 8 + (lane & 3) * 2;
            if (MODE == 0) {
                *(float2*)(C + (size_t)r * ldc + c) = make_float2(v0, v1);
                *(float2*)(C + (size_t)(r + 8) * ldc + c) = make_float2(v2, v3);
            } else {
                qkv_store(r, c, v0, v1, tbl, qh, kh, vh);
                qkv_store(r + 8, c, v2, v3, tbl, qh, kh, vh);
            }
        }
    }
}

// ---------------------------------------------------------------------------
// Tensor-core causal flash attention, pure fp16 operands / fp32 accum.
// Main loop: kt in [0, qt) — NO mask, NO conditionals (round-12 hot path).
// Diagonal tile peeled into a dedicated tail block with per-warp causal
// skip (warp w touches only key blocks p <= w; skipped blocks contributed
// exact zeros before).
// grid = (B*H, S/128) with qt reversed (longest CTAs first), 256 threads.
// SMEM: Qh (16KB) + 2-stage {Kh,Vh} (2x32KB) = 80KB.
// ---------------------------------------------------------------------------
#define FA_STAGE 32768
#define FA_SMEM (16384 + 2 * FA_STAGE)

__device__ __forceinline__ void fa_load_kv(
    uint32_t base, const __half* kh, const __half* vh,
    int kt, int cm, int cc) {
    const __half* srcs[2] = { kh, vh };
#pragma unroll
    for (int tt = 0; tt < 2; tt++) {
#pragma unroll
        for (int j = 0; j < 4; j++) {
            int r = cm + 32 * j;
            cp16(base + tt * 16384 + SWZ(r * 128 + cc * 16),
                 srcs[tt] + (size_t)(kt * 128 + r) * KD + cc * 8);
        }
    }
    CP_COMMIT();
}

__global__ __launch_bounds__(256, 1)
void flash_mma(const __half* __restrict__ qh,
               const __half* __restrict__ kh, const __half* __restrict__ vh,
               __half* __restrict__ yhp) {
    extern __shared__ __align__(1024) char sm[];
    const uint32_t sb = smem_u32(sm);
    const int t = threadIdx.x, lane = t & 31, w = t >> 5;
    const int bh = blockIdx.x;
    const int qt = (int)gridDim.y - 1 - (int)blockIdx.y;   // longest first
    const size_t ho = (size_t)bh * SV * KD;

    const int cm = t >> 3, cc = t & 7;

    // group 0: Q tile
    {
        const __half* qsrc = qh + ho + (size_t)qt * 128 * KD;
#pragma unroll
        for (int j = 0; j < 4; j++) {
            int r = cm + 32 * j;
            cp16(sb + SWZ(r * 128 + cc * 16), qsrc + (size_t)r * KD + cc * 8);
        }
        CP_COMMIT();
    }
    // group 1: KV tile 0
    fa_load_kv(sb + 16384, kh + ho, vh + ho, 0, cm, cc);

    const int sub = lane >> 3, l7 = lane & 7;

    // Q fragments (hoisted out of the loop: wait for Q group only)
    uint32_t qfh[4][4];
    CP_WAIT1();
    __syncthreads();
    {
        const int rA = w * 16 + ((sub & 1) << 3) + l7;
        const int kA = sub >> 1;
#pragma unroll
        for (int kc = 0; kc < 4; kc++)
            ldm4(qfh[kc], sb + SWZ(rA * 128 + (kc * 2 + kA) * 16));
    }

    float m0 = -3.0e38f, m1 = -3.0e38f, l0 = 0.0f, l1 = 0.0f;
    float yacc[8][4];
#pragma unroll
    for (int p = 0; p < 8; p++)
#pragma unroll
        for (int e = 0; e < 4; e++) yacc[p][e] = 0.0f;

    const int rB = ((sub >> 1) << 3) + l7;
    const int kB = sub & 1;
    const int vr = ((lane >> 3) & 1) * 8 + (lane & 7);
    const int vc = (lane >> 4) * 8;

    // ---- main loop: full (non-diagonal) key tiles, branch-free body ----
    for (int kt = 0; kt < qt; kt++) {
        const int st = kt & 1;
        CP_WAIT0();
        __syncthreads();
        fa_load_kv(sb + 16384 + (st ^ 1) * FA_STAGE,
                   kh + ho, vh + ho, kt + 1, cm, cc);

        const uint32_t KhB = sb + 16384 + st * FA_STAGE;
        const uint32_t VhB = KhB + 16384;

        // S = Q K^T
        float sacc[16][4];
#pragma unroll
        for (int n8 = 0; n8 < 16; n8++)
#pragma unroll
            for (int e = 0; e < 4; e++) sacc[n8][e] = 0.0f;

#pragma unroll
        for (int kc = 0; kc < 4; kc++) {
#pragma unroll
            for (int p = 0; p < 8; p++) {
                uint32_t off = SWZ((p * 16 + rB) * 128 + (kc * 2 + kB) * 16);
                uint32_t kh4[4];
                ldm4(kh4, KhB + off);
                mma_f32(sacc[2 * p], qfh[kc], kh4[0], kh4[1]);
                mma_f32(sacc[2 * p + 1], qfh[kc], kh4[2], kh4[3]);
            }
        }

        // online softmax
        float mx0 = -3.0e38f, mx1 = -3.0e38f;
#pragma unroll
        for (int n8 = 0; n8 < 16; n8++) {
            mx0 = fmaxf(mx0, fmaxf(sacc[n8][0], sacc[n8][1]));
            mx1 = fmaxf(mx1, fmaxf(sacc[n8][2], sacc[n8][3]));
        }
        mx0 = fmaxf(mx0, __shfl_xor_sync(0xffffffffu, mx0, 1));
        mx0 = fmaxf(mx0, __shfl_xor_sync(0xffffffffu, mx0, 2));
        mx1 = fmaxf(mx1, __shfl_xor_sync(0xffffffffu, mx1, 1));
        mx1 = fmaxf(mx1, __shfl_xor_sync(0xffffffffu, mx1, 2));
        const float mt0 = fmaxf(m0, mx0), mt1 = fmaxf(m1, mx1);
        const float sc0 = __expf(m0 - mt0), sc1 = __expf(m1 - mt1);
        l0 *= sc0; l1 *= sc1;
#pragma unroll
        for (int p = 0; p < 8; p++) {
            yacc[p][0] *= sc0; yacc[p][1] *= sc0;
            yacc[p][2] *= sc1; yacc[p][3] *= sc1;
        }
        m0 = mt0; m1 = mt1;

        uint32_t aH[8][4];
        float rs0 = 0.0f, rs1 = 0.0f;
#pragma unroll
        for (int kc = 0; kc < 8; kc++) {
#pragma unroll
            for (int e = 0; e < 2; e++) {
                const int n8 = 2 * kc + e;
                float p0 = __expf(sacc[n8][0] - mt0);
                float p1 = __expf(sacc[n8][1] - mt0);
                float p2 = __expf(sacc[n8][2] - mt1);
                float p3 = __expf(sacc[n8][3] - mt1);
                rs0 += p0 + p1; rs1 += p2 + p3;
                aH[kc][2 * e]     = b2u(__floats2half2_rn(p0, p1));
                aH[kc][2 * e + 1] = b2u(__floats2half2_rn(p2, p3));
            }
        }
        rs0 += __shfl_xor_sync(0xffffffffu, rs0, 1);
        rs0 += __shfl_xor_sync(0xffffffffu, rs0, 2);
        rs1 += __shfl_xor_sync(0xffffffffu, rs1, 1);
        rs1 += __shfl_xor_sync(0xffffffffu, rs1, 2);
        l0 += rs0; l1 += rs1;

        // Y += P V
#pragma unroll
        for (int kc = 0; kc < 8; kc++) {
#pragma unroll
            for (int p = 0; p < 4; p++) {
                uint32_t off = SWZ((kc * 16 + vr) * 128 + (p * 16 + vc) * 2);
                uint32_t vh4[4];
                ldm4t(vh4, VhB + off);
                mma_f32(yacc[2 * p], aH[kc], vh4[0], vh4[1]);
                mma_f32(yacc[2 * p + 1], aH[kc], vh4[2], vh4[3]);
            }
        }
        __syncthreads();
    }

    // ---- diagonal tile (kt == qt): per-warp causal skip ----
    {
        const int st = qt & 1;
        CP_WAIT0();
        __syncthreads();

        const uint32_t KhB = sb + 16384 + st * FA_STAGE;
        const uint32_t VhB = KhB + 16384;
        const int nact = (w + 1) << 1;   // active n8 blocks for warp w

        float sacc[16][4];
#pragma unroll
        for (int n8 = 0; n8 < 16; n8++)
#pragma unroll
            for (int e = 0; e < 4; e++) sacc[n8][e] = 0.0f;

#pragma unroll
        for (int kc = 0; kc < 4; kc++) {
            for (int p = 0; p <= w; p++) {
                uint32_t off = SWZ((p * 16 + rB) * 128 + (kc * 2 + kB) * 16);
                uint32_t kh4[4];
                ldm4(kh4, KhB + off);
                mma_f32(sacc[2 * p], qfh[kc], kh4[0], kh4[1]);
                mma_f32(sacc[2 * p + 1], qfh[kc], kh4[2], kh4[3]);
            }
        }

        // causal mask (within active blocks)
        const int rr0 = w * 16 + (lane >> 2);
#pragma unroll
        for (int n8 = 0; n8 < 16; n8++) {
            if (n8 < nact) {
                int cb = n8 * 8 + (lane & 3) * 2;
                if (cb     > rr0)     sacc[n8][0] = -1e30f;
                if (cb + 1 > rr0)     sacc[n8][1] = -1e30f;
                if (cb     > rr0 + 8) sacc[n8][2] = -1e30f;
                if (cb + 1 > rr0 + 8) sacc[n8][3] = -1e30f;
            }
        }

        float mx0 = -3.0e38f, mx1 = -3.0e38f;
#pragma unroll
        for (int n8 = 0; n8 < 16; n8++) {
            if (n8 < nact) {
                mx0 = fmaxf(mx0, fmaxf(sacc[n8][0], sacc[n8][1]));
                mx1 = fmaxf(mx1, fmaxf(sacc[n8][2], sacc[n8][3]));
            }
        }
        mx0 = fmaxf(mx0, __shfl_xor_sync(0xffffffffu, mx0, 1));
        mx0 = fmaxf(mx0, __shfl_xor_sync(0xffffffffu, mx0, 2));
        mx1 = fmaxf(mx1, __shfl_xor_sync(0xffffffffu, mx1, 1));
        mx1 = fmaxf(mx1, __shfl_xor_sync(0xffffffffu, mx1, 2));
        const float mt0 = fmaxf(m0, mx0), mt1 = fmaxf(m1, mx1);
        const float sc0 = __expf(m0 - mt0), sc1 = __expf(m1 - mt1);
        l0 *= sc0; l1 *= sc1;
#pragma unroll
        for (int p = 0; p < 8; p++) {
            yacc[p][0] *= sc0; yacc[p][1] *= sc0;
            yacc[p][2] *= sc1; yacc[p][3] *= sc1;
        }
        m0 = mt0; m1 = mt1;

        uint32_t aH[8][4];
        float rs0 = 0.0f, rs1 = 0.0f;
        for (int kc = 0; kc <= w; kc++) {
#pragma unroll
            for (int e = 0; e < 2; e++) {
                const int n8 = 2 * kc + e;
                float p0 = __expf(sacc[n8][0] - mt0);
                float p1 = __expf(sacc[n8][1] - mt0);
                float p2 = __expf(sacc[n8][2] - mt1);
                float p3 = __expf(sacc[n8][3] - mt1);
                rs0 += p0 + p1; rs1 += p2 + p3;
                aH[kc][2 * e]     = b2u(__floats2half2_rn(p0, p1));
                aH[kc][2 * e + 1] = b2u(__floats2half2_rn(p2, p3));
            }
        }
        rs0 += __shfl_xor_sync(0xffffffffu, rs0, 1);
        rs0 += __shfl_xor_sync(0xffffffffu, rs0, 2);
        rs1 += __shfl_xor_sync(0xffffffffu, rs1, 1);
        rs1 += __shfl_xor_sync(0xffffffffu, rs1, 2);
        l0 += rs0; l1 += rs1;

        for (int kc = 0; kc <= w; kc++) {
#pragma unroll
            for (int p = 0; p < 4; p++) {
                uint32_t off = SWZ((kc * 16 + vr) * 128 + (p * 16 + vc) * 2);
                uint32_t vh4[4];
                ldm4t(vh4, VhB + off);
                mma_f32(yacc[2 * p], aH[kc], vh4[0], vh4[1]);
                mma_f32(yacc[2 * p + 1], aH[kc], vh4[2], vh4[3]);
            }
        }
    }

    // epilogue: normalize, fp16 convert, write [B,S,D]
    const float il0 = 1.0f / l0, il1 = 1.0f / l1;
    const int b = bh / HV, h = bh % HV;
    const int gr0 = qt * 128 + w * 16 + (lane >> 2);
    const size_t o0 = ((size_t)(b * SV) + gr0) * DV + h * KD;
    const size_t o1 = o0 + (size_t)8 * DV;
#pragma unroll
    for (int p = 0; p < 8; p++) {
        int c = p * 8 + (lane & 3) * 2;
        *(__half2*)(yhp + o0 + c) = __floats2half2_rn(yacc[p][0] * il0, yacc[p][1] * il0);
        *(__half2*)(yhp + o1 + c) = __floats2half2_rn(yacc[p][2] * il1, yacc[p][3] * il1);
    }
}

// ---------------------------------------------------------------------------
// kernel_launch
// ---------------------------------------------------------------------------
extern "C" void kernel_launch(void* const* d_in, const int* in_sizes, int n_in,
                              void* d_out, int out_size) {
    (void)in_sizes; (void)n_in; (void)out_size;
    const float* x  = (const float*)d_in[0];
    const float* Wq = (const float*)d_in[2];
    const float* Wk = (const float*)d_in[3];
    const float* Wv = (const float*)d_in[4];
    const float* Wo = (const float*)d_in[5];
    float* out = (float*)d_out;

    float* tbl;
    __half *xh, *wh, *qh, *kh, *vh, *yh;
    cudaGetSymbolAddress((void**)&tbl, g_rope);
    cudaGetSymbolAddress((void**)&xh, g_xh);
    cudaGetSymbolAddress((void**)&wh, g_wh);
    cudaGetSymbolAddress((void**)&qh, g_qh);
    cudaGetSymbolAddress((void**)&kh, g_kh);
    cudaGetSymbolAddress((void**)&vh, g_vh);
    cudaGetSymbolAddress((void**)&yh, g_yh);

    cudaFuncSetAttribute(mma_gemm<0>, cudaFuncAttributeMaxDynamicSharedMemorySize, GEMM_SMEM);
    cudaFuncSetAttribute(mma_gemm<1>, cudaFuncAttributeMaxDynamicSharedMemorySize, GEMM_SMEM);
    cudaFuncSetAttribute(flash_mma, cudaFuncAttributeMaxDynamicSharedMemorySize, FA_SMEM);

    // fused prelude: x convert + weight transpose/convert + rope table
    prelude_kernel<<<NB_TOHALF + NB_TRANS + NB_ROPE, 256>>>(
        x, Wq, Wk, Wv, Wo, xh, wh, tbl);

    // fused QKV projection (N = 3072) with fused rope/repack epilogue
    dim3 qkvgrid(3 * DV / GBN, MROWS / GBM);   // (24, 32)
    mma_gemm<1><<<qkvgrid, 512, GEMM_SMEM>>>(xh, wh, nullptr, 0,
                                             tbl, qh, kh, vh);

    // tensor-core flash attention (longest CTAs scheduled first)
    dim3 fgrid(BV * HV, SV / 128);             // (32, 16)
    flash_mma<<<fgrid, 256, FA_SMEM>>>(qh, kh, vh, yh);

    // output projection
    dim3 ogrid(DV / GBN, MROWS / GBM);         // (8, 32)
    mma_gemm<0><<<ogrid, 512, GEMM_SMEM>>>(yh, wh + 3 * (size_t)DV * DV,
                                           out, DV,
                                           nullptr, nullptr, nullptr, nullptr);
}

// round 14
// speedup vs baseline: 1.0131x; 1.0131x over previous
#include <cuda_runtime.h>
#include <cuda_fp16.h>
#include <math.h>
#include <stdint.h>
#include <string.h>

// ---------------------------------------------------------------------------
// Problem constants: B=2, S=2048, D=1024, H=16, head_dim=64, rope dims=32
// ---------------------------------------------------------------------------
#define BV 2
#define HV 16
#define SV 2048
#define DV 1024
#define KD 64
#define MROWS (BV*SV)        // 4096
#define HEADROWS (BV*HV*SV)  // 65536

// Scratch (device globals: allocation-free rule)
__device__ float g_rope[SV * 16 * 2];     // (sin, cos) per (s, pair)
__device__ __half g_xh[MROWS * DV];
__device__ __half g_wh[4 * DV * DV];
__device__ __half g_qh[HEADROWS * KD];
__device__ __half g_kh[HEADROWS * KD];
__device__ __half g_vh[HEADROWS * KD];
__device__ __half g_yh[MROWS * DV];

// ---------------------------------------------------------------------------
// helpers
// ---------------------------------------------------------------------------
__device__ __forceinline__ uint32_t smem_u32(const void* p) {
    uint32_t a;
    asm("{ .reg .u64 t; cvta.to.shared.u64 t, %1; cvt.u32.u64 %0, t; }"
        : "=r"(a) : "l"(p));
    return a;
}

#define SWZ(o) ((o) ^ (((o) >> 3) & 0x70))

__device__ __forceinline__ void ldm4(uint32_t* r, uint32_t addr) {
    asm volatile("ldmatrix.sync.aligned.m8n8.x4.shared.b16 {%0,%1,%2,%3}, [%4];"
                 : "=r"(r[0]), "=r"(r[1]), "=r"(r[2]), "=r"(r[3]) : "r"(addr));
}

__device__ __forceinline__ void ldm4t(uint32_t* r, uint32_t addr) {
    asm volatile("ldmatrix.sync.aligned.m8n8.x4.trans.shared.b16 {%0,%1,%2,%3}, [%4];"
                 : "=r"(r[0]), "=r"(r[1]), "=r"(r[2]), "=r"(r[3]) : "r"(addr));
}

// f32-accumulate fp16 mma
__device__ __forceinline__ void mma_f32(float* c, const uint32_t* a,
                                        uint32_t b0, uint32_t b1) {
    asm volatile(
        "mma.sync.aligned.m16n8k16.row.col.f32.f16.f16.f32 "
        "{%0,%1,%2,%3},{%4,%5,%6,%7},{%8,%9},{%0,%1,%2,%3};"
        : "+f"(c[0]), "+f"(c[1]), "+f"(c[2]), "+f"(c[3])
        : "r"(a[0]), "r"(a[1]), "r"(a[2]), "r"(a[3]), "r"(b0), "r"(b1));
}

__device__ __forceinline__ void cp16(uint32_t saddr, const void* gaddr) {
    asm volatile("cp.async.cg.shared.global [%0], [%1], 16;"
                 :: "r"(saddr), "l"(gaddr) : "memory");
}
#define CP_COMMIT() asm volatile("cp.async.commit_group;" ::: "memory")
#define CP_WAIT2()  asm volatile("cp.async.wait_group 2;" ::: "memory")
#define CP_WAIT1()  asm volatile("cp.async.wait_group 1;" ::: "memory")
#define CP_WAIT0()  asm volatile("cp.async.wait_group 0;" ::: "memory")

__device__ __forceinline__ uint32_t b2u(__half2 v) {
    uint32_t u;
    memcpy(&u, &v, 4);
    return u;
}

// ---------------------------------------------------------------------------
// Fused prelude: one launch, region-decoded grid.
//   blocks [0,4096)      : x fp32 -> fp16
//   blocks [4096,8192)   : weight transpose + scale + fp16 (4 weights)
//   blocks [8192,8320)   : RoPE sin/cos table
// ---------------------------------------------------------------------------
#define NB_TOHALF 4096
#define NB_TRANS  4096
#define NB_ROPE   128

__global__ __launch_bounds__(256)
void prelude_kernel(const float* __restrict__ x,
                    const float* __restrict__ W0, const float* __restrict__ W1,
                    const float* __restrict__ W2, const float* __restrict__ W3,
                    __half* __restrict__ xh, __half* __restrict__ wh_all,
                    float* __restrict__ tbl) {
    const int bid = blockIdx.x;
    const int t = threadIdx.x;
    __shared__ float tile[32][33];

    if (bid < NB_TOHALF) {
        int i = bid * 256 + t;
        float4 v = ((const float4*)x)[i];
        *(__half2*)(xh + 4 * i)     = __floats2half2_rn(v.x, v.y);
        *(__half2*)(xh + 4 * i + 2) = __floats2half2_rn(v.z, v.w);
        return;
    }
    if (bid < NB_TOHALF + NB_TRANS) {
        int r = bid - NB_TOHALF;
        int widx = r >> 10;
        int rr = r & 1023;
        int bx = (rr & 31) * 32, by = (rr >> 5) * 32;
        const float* Ws[4] = { W0, W1, W2, W3 };
        const float* W = Ws[widx];
        const float scale = (widx == 0) ? 0.125f : 1.0f;
        __half* hi = wh_all + (size_t)widx * DV * DV;
        int tx = t & 31, ty = t >> 5;
#pragma unroll
        for (int q = 0; q < 32; q += 8)
            tile[ty + q][tx] = W[(size_t)(by + ty + q) * DV + bx + tx];
        __syncthreads();
#pragma unroll
        for (int q = 0; q < 32; q += 8)
            hi[(size_t)(bx + ty + q) * DV + by + tx] =
                __float2half_rn(tile[tx][ty + q] * scale);
        return;
    }
    {
        int idx = (bid - NB_TOHALF - NB_TRANS) * 256 + t;
        int i = idx & 15, s = idx >> 4;
        float inv = powf(10000.0f, -(float)i / 16.0f);
        float sn, cs;
        sincosf((float)s * inv, &sn, &cs);
        tbl[2 * idx]     = sn;
        tbl[2 * idx + 1] = cs;
    }
}

// ---------------------------------------------------------------------------
// fp16 GEMM (f32 accumulate): C = Ah @ Bh^T.   (round-9/12 proven config)
// 128x128 block tile, BK=64, 3-stage cp.async pipeline, 512 threads
// (16 warps, 4x4, 32x32 warp tile).
// MODE 0: plain fp32 C output.
// MODE 1: fused QKV epilogue — RoPE + fp16 convert + head-major repack.
// ---------------------------------------------------------------------------
#define GBM 128
#define GBN 128
#define GBK 64
#define TILE_BYTES (GBM * GBK * 2)
#define STAGE_BYTES (2 * TILE_BYTES)      // Ah, Bh
#define NSTAGE 3
#define GEMM_SMEM (NSTAGE * STAGE_BYTES)  // 98304
#define NITER (DV / GBK)                  // 16

__device__ __forceinline__ void qkv_store(
    int r, int c, float v0, float v1, const float* __restrict__ tbl,
    __half* __restrict__ qh, __half* __restrict__ kh, __half* __restrict__ vh) {
    const int b = r >> 11, s = r & (SV - 1);
    const int tt = c >> 10;              // 0=q, 1=k, 2=v
    const int cd = c & (DV - 1);
    const int h = cd >> 6, d = cd & (KD - 1);
    if (tt < 2 && d < 32) {
        float2 sc = *(const float2*)(tbl + (size_t)(s * 16 + (d >> 1)) * 2);
        float a = v0 * sc.y - v1 * sc.x;
        float bq = v1 * sc.y + v0 * sc.x;
        v0 = a; v1 = bq;
    }
    const size_t o = (((size_t)(b * HV + h)) * SV + s) * KD + d;
    __half* dst = (tt == 0) ? qh : (tt == 1) ? kh : vh;
    *(__half2*)(dst + o) = __floats2half2_rn(v0, v1);
}

template <int MODE>
__global__ __launch_bounds__(512, 1)
void mma_gemm(const __half* __restrict__ Ah,
              const __half* __restrict__ Bh,
              float* __restrict__ C, int ldc,
              const float* __restrict__ tbl,
              __half* __restrict__ qh, __half* __restrict__ kh,
              __half* __restrict__ vh) {
    extern __shared__ __align__(1024) char sm[];
    const uint32_t sb = smem_u32(sm);
    const int t = threadIdx.x;
    const int lane = t & 31, wid = t >> 5;
    const int warpM = wid & 3, warpN = wid >> 2;
    const int row0 = blockIdx.y * GBM;
    const int col0 = blockIdx.x * GBN;

    const __half* srcs[2] = { Ah + (size_t)row0 * DV, Bh + (size_t)col0 * DV };

    const int cm = t >> 3;        // 0..63
    const int cc = t & 7;

    float accF[2][4][4];
#pragma unroll
    for (int i = 0; i < 2; i++)
#pragma unroll
        for (int j = 0; j < 4; j++)
#pragma unroll
            for (int r = 0; r < 4; r++) accF[i][j][r] = 0.0f;

    const int sub = lane >> 3, l7 = lane & 7;
    const int rowA0 = warpM * 32 + ((sub & 1) << 3) + l7;
    const int rowA1 = rowA0 + 16;
    const int kA = (sub >> 1);
    int rowB[2];
#pragma unroll
    for (int p = 0; p < 2; p++)
        rowB[p] = warpN * 32 + p * 16 + ((sub >> 1) << 3) + l7;
    const int kB = (sub & 1);

    auto issue = [&](int st) {
        const int k0 = st * GBK;
        const uint32_t stb = sb + (st % NSTAGE) * STAGE_BYTES;
#pragma unroll
        for (int tile = 0; tile < 2; tile++) {
#pragma unroll
            for (int j = 0; j < 2; j++) {
                int m = cm + 64 * j;
                cp16(stb + tile * TILE_BYTES + SWZ(m * 128 + cc * 16),
                     srcs[tile] + (size_t)m * DV + k0 + cc * 8);
            }
        }
        CP_COMMIT();
    };

    issue(0);
    issue(1);

    for (int it = 0; it < NITER; it++) {
        if (it == NITER - 1) { CP_WAIT0(); } else { CP_WAIT1(); }
        __syncthreads();
        if (it + 2 < NITER) issue(it + 2);

        const uint32_t ahB = sb + (it % NSTAGE) * STAGE_BYTES;
        const uint32_t bhB = ahB + TILE_BYTES;

#pragma unroll
        for (int ks = 0; ks < 4; ks++) {
            const int kcA = ks * 2 + kA;
            const int kcB = ks * 2 + kB;
            uint32_t ah[2][4];
            ldm4(ah[0], ahB + SWZ(rowA0 * 128 + kcA * 16));
            ldm4(ah[1], ahB + SWZ(rowA1 * 128 + kcA * 16));
            uint32_t bh[2][4];
#pragma unroll
            for (int p = 0; p < 2; p++)
                ldm4(bh[p], bhB + SWZ(rowB[p] * 128 + kcB * 16));
#pragma unroll
            for (int mt = 0; mt < 2; mt++) {
#pragma unroll
                for (int nt = 0; nt < 4; nt++) {
                    const int p = nt >> 1, o = (nt & 1) * 2;
                    mma_f32(accF[mt][nt], ah[mt], bh[p][o], bh[p][o + 1]);
                }
            }
        }
    }

#pragma unroll
    for (int mt = 0; mt < 2; mt++) {
#pragma unroll
        for (int nt = 0; nt < 4; nt++) {
            float v0 = accF[mt][nt][0], v1 = accF[mt][nt][1];
            float v2 = accF[mt][nt][2], v3 = accF[mt][nt][3];
            int r = row0 + warpM * 32 + mt * 16 + (lane >> 2);
            int c = col0 + warpN * 32 + nt * 8 + (lane & 3) * 2;
            if (MODE == 0) {
                *(float2*)(C + (size_t)r * ldc + c) = make_float2(v0, v1);
                *(float2*)(C + (size_t)(r + 8) * ldc + c) = make_float2(v2, v3);
            } else {
                qkv_store(r, c, v0, v1, tbl, qh, kh, vh);
                qkv_store(r + 8, c, v2, v3, tbl, qh, kh, vh);
            }
        }
    }
}

// ---------------------------------------------------------------------------
// Tensor-core causal flash attention, pure fp16 operands / fp32 accum.
// Round-12 compute body (branch-light, mask on diagonal), upgraded to a
// 3-stage KV ring: one full KV tile of load slack always in flight.
// grid = (B*H, S/128) with qt reversed (longest CTAs first), 256 threads.
// SMEM: Qh (16KB) + 3-stage {Kh,Vh} (3x32KB) = 112KB.
// ---------------------------------------------------------------------------
#define FA_STAGE 32768
#define FA_NSTAGE 3
#define FA_SMEM (16384 + FA_NSTAGE * FA_STAGE)

__device__ __forceinline__ void fa_load_kv(
    uint32_t base, const __half* kh, const __half* vh,
    int kt, int cm, int cc) {
    const __half* srcs[2] = { kh, vh };
#pragma unroll
    for (int tt = 0; tt < 2; tt++) {
#pragma unroll
        for (int j = 0; j < 4; j++) {
            int r = cm + 32 * j;
            cp16(base + tt * 16384 + SWZ(r * 128 + cc * 16),
                 srcs[tt] + (size_t)(kt * 128 + r) * KD + cc * 8);
        }
    }
    CP_COMMIT();
}

__global__ __launch_bounds__(256, 1)
void flash_mma(const __half* __restrict__ qh,
               const __half* __restrict__ kh, const __half* __restrict__ vh,
               __half* __restrict__ yhp) {
    extern __shared__ __align__(1024) char sm[];
    const uint32_t sb = smem_u32(sm);
    const int t = threadIdx.x, lane = t & 31, w = t >> 5;
    const int bh = blockIdx.x;
    const int qt = (int)gridDim.y - 1 - (int)blockIdx.y;   // longest first
    const size_t ho = (size_t)bh * SV * KD;
    const int nt = qt + 1;

    const int cm = t >> 3, cc = t & 7;

    // group: Q tile
    {
        const __half* qsrc = qh + ho + (size_t)qt * 128 * KD;
#pragma unroll
        for (int j = 0; j < 4; j++) {
            int r = cm + 32 * j;
            cp16(sb + SWZ(r * 128 + cc * 16), qsrc + (size_t)r * KD + cc * 8);
        }
        CP_COMMIT();
    }
    // groups: KV tile 0 (+ KV tile 1 if it exists)
    fa_load_kv(sb + 16384, kh + ho, vh + ho, 0, cm, cc);
    if (nt > 1)
        fa_load_kv(sb + 16384 + FA_STAGE, kh + ho, vh + ho, 1, cm, cc);

    const int sub = lane >> 3, l7 = lane & 7;

    // Q fragments (wait for Q group only; KV groups stay in flight)
    uint32_t qfh[4][4];
    if (nt > 1) { CP_WAIT2(); } else { CP_WAIT1(); }
    __syncthreads();
    {
        const int rA = w * 16 + ((sub & 1) << 3) + l7;
        const int kA = sub >> 1;
#pragma unroll
        for (int kc = 0; kc < 4; kc++)
            ldm4(qfh[kc], sb + SWZ(rA * 128 + (kc * 2 + kA) * 16));
    }

    float m0 = -3.0e38f, m1 = -3.0e38f, l0 = 0.0f, l1 = 0.0f;
    float yacc[8][4];
#pragma unroll
    for (int p = 0; p < 8; p++)
#pragma unroll
        for (int e = 0; e < 4; e++) yacc[p][e] = 0.0f;

    const int rB = ((sub >> 1) << 3) + l7;
    const int kB = sub & 1;
    const int vr = ((lane >> 3) & 1) * 8 + (lane & 7);
    const int vc = (lane >> 4) * 8;

    for (int kt = 0; kt < nt; kt++) {
        if (kt + 1 == nt) { CP_WAIT0(); } else { CP_WAIT1(); }
        __syncthreads();
        if (kt + 2 < nt)
            fa_load_kv(sb + 16384 + ((kt + 2) % FA_NSTAGE) * FA_STAGE,
                       kh + ho, vh + ho, kt + 2, cm, cc);

        const uint32_t KhB = sb + 16384 + (kt % FA_NSTAGE) * FA_STAGE;
        const uint32_t VhB = KhB + 16384;

        // ---- S = Q K^T ----
        float sacc[16][4];
#pragma unroll
        for (int n8 = 0; n8 < 16; n8++)
#pragma unroll
            for (int e = 0; e < 4; e++) sacc[n8][e] = 0.0f;

#pragma unroll
        for (int kc = 0; kc < 4; kc++) {
#pragma unroll
            for (int p = 0; p < 8; p++) {
                uint32_t off = SWZ((p * 16 + rB) * 128 + (kc * 2 + kB) * 16);
                uint32_t kh4[4];
                ldm4(kh4, KhB + off);
                mma_f32(sacc[2 * p], qfh[kc], kh4[0], kh4[1]);
                mma_f32(sacc[2 * p + 1], qfh[kc], kh4[2], kh4[3]);
            }
        }

        // causal mask on diagonal tile
        const int rr0 = w * 16 + (lane >> 2);
        if (kt == qt) {
#pragma unroll
            for (int n8 = 0; n8 < 16; n8++) {
                int cb = n8 * 8 + (lane & 3) * 2;
                if (cb     > rr0)     sacc[n8][0] = -1e30f;
                if (cb + 1 > rr0)     sacc[n8][1] = -1e30f;
                if (cb     > rr0 + 8) sacc[n8][2] = -1e30f;
                if (cb + 1 > rr0 + 8) sacc[n8][3] = -1e30f;
            }
        }

        // ---- online softmax ----
        float mx0 = -3.0e38f, mx1 = -3.0e38f;
#pragma unroll
        for (int n8 = 0; n8 < 16; n8++) {
            mx0 = fmaxf(mx0, fmaxf(sacc[n8][0], sacc[n8][1]));
            mx1 = fmaxf(mx1, fmaxf(sacc[n8][2], sacc[n8][3]));
        }
        mx0 = fmaxf(mx0, __shfl_xor_sync(0xffffffffu, mx0, 1));
        mx0 = fmaxf(mx0, __shfl_xor_sync(0xffffffffu, mx0, 2));
        mx1 = fmaxf(mx1, __shfl_xor_sync(0xffffffffu, mx1, 1));
        mx1 = fmaxf(mx1, __shfl_xor_sync(0xffffffffu, mx1, 2));
        const float mt0 = fmaxf(m0, mx0), mt1 = fmaxf(m1, mx1);
        const float sc0 = __expf(m0 - mt0), sc1 = __expf(m1 - mt1);
        l0 *= sc0; l1 *= sc1;
#pragma unroll
        for (int p = 0; p < 8; p++) {
            yacc[p][0] *= sc0; yacc[p][1] *= sc0;
            yacc[p][2] *= sc1; yacc[p][3] *= sc1;
        }
        m0 = mt0; m1 = mt1;

        // p = exp(s - m) -> fp16 A-fragments
        uint32_t aH[8][4];
        float rs0 = 0.0f, rs1 = 0.0f;
#pragma unroll
        for (int kc = 0; kc < 8; kc++) {
#pragma unroll
            for (int e = 0; e < 2; e++) {
                const int n8 = 2 * kc + e;
                float p0 = __expf(sacc[n8][0] - mt0);
                float p1 = __expf(sacc[n8][1] - mt0);
                float p2 = __expf(sacc[n8][2] - mt1);
                float p3 = __expf(sacc[n8][3] - mt1);
                rs0 += p0 + p1; rs1 += p2 + p3;
                aH[kc][2 * e]     = b2u(__floats2half2_rn(p0, p1));
                aH[kc][2 * e + 1] = b2u(__floats2half2_rn(p2, p3));
            }
        }
        rs0 += __shfl_xor_sync(0xffffffffu, rs0, 1);
        rs0 += __shfl_xor_sync(0xffffffffu, rs0, 2);
        rs1 += __shfl_xor_sync(0xffffffffu, rs1, 1);
        rs1 += __shfl_xor_sync(0xffffffffu, rs1, 2);
        l0 += rs0; l1 += rs1;

        // ---- Y += P V ----
#pragma unroll
        for (int kc = 0; kc < 8; kc++) {
#pragma unroll
            for (int p = 0; p < 4; p++) {
                uint32_t off = SWZ((kc * 16 + vr) * 128 + (p * 16 + vc) * 2);
                uint32_t vh4[4];
                ldm4t(vh4, VhB + off);
                mma_f32(yacc[2 * p], aH[kc], vh4[0], vh4[1]);
                mma_f32(yacc[2 * p + 1], aH[kc], vh4[2], vh4[3]);
            }
        }
        __syncthreads();
    }

    // epilogue: normalize, fp16 convert, write [B,S,D]
    const float il0 = 1.0f / l0, il1 = 1.0f / l1;
    const int b = bh / HV, h = bh % HV;
    const int gr0 = qt * 128 + w * 16 + (lane >> 2);
    const size_t o0 = ((size_t)(b * SV) + gr0) * DV + h * KD;
    const size_t o1 = o0 + (size_t)8 * DV;
#pragma unroll
    for (int p = 0; p < 8; p++) {
        int c = p * 8 + (lane & 3) * 2;
        *(__half2*)(yhp + o0 + c) = __floats2half2_rn(yacc[p][0] * il0, yacc[p][1] * il0);
        *(__half2*)(yhp + o1 + c) = __floats2half2_rn(yacc[p][2] * il1, yacc[p][3] * il1);
    }
}

// ---------------------------------------------------------------------------
// kernel_launch
// ---------------------------------------------------------------------------
extern "C" void kernel_launch(void* const* d_in, const int* in_sizes, int n_in,
                              void* d_out, int out_size) {
    (void)in_sizes; (void)n_in; (void)out_size;
    const float* x  = (const float*)d_in[0];
    const float* Wq = (const float*)d_in[2];
    const float* Wk = (const float*)d_in[3];
    const float* Wv = (const float*)d_in[4];
    const float* Wo = (const float*)d_in[5];
    float* out = (float*)d_out;

    float* tbl;
    __half *xh, *wh, *qh, *kh, *vh, *yh;
    cudaGetSymbolAddress((void**)&tbl, g_rope);
    cudaGetSymbolAddress((void**)&xh, g_xh);
    cudaGetSymbolAddress((void**)&wh, g_wh);
    cudaGetSymbolAddress((void**)&qh, g_qh);
    cudaGetSymbolAddress((void**)&kh, g_kh);
    cudaGetSymbolAddress((void**)&vh, g_vh);
    cudaGetSymbolAddress((void**)&yh, g_yh);

    cudaFuncSetAttribute(mma_gemm<0>, cudaFuncAttributeMaxDynamicSharedMemorySize, GEMM_SMEM);
    cudaFuncSetAttribute(mma_gemm<1>, cudaFuncAttributeMaxDynamicSharedMemorySize, GEMM_SMEM);
    cudaFuncSetAttribute(flash_mma, cudaFuncAttributeMaxDynamicSharedMemorySize, FA_SMEM);

    // fused prelude: x convert + weight transpose/convert + rope table
    prelude_kernel<<<NB_TOHALF + NB_TRANS + NB_ROPE, 256>>>(
        x, Wq, Wk, Wv, Wo, xh, wh, tbl);

    // fused QKV projection (N = 3072) with fused rope/repack epilogue
    dim3 qkvgrid(3 * DV / GBN, MROWS / GBM);   // (24, 32)
    mma_gemm<1><<<qkvgrid, 512, GEMM_SMEM>>>(xh, wh, nullptr, 0,
                                             tbl, qh, kh, vh);

    // tensor-core flash attention (longest CTAs scheduled first)
    dim3 fgrid(BV * HV, SV / 128);             // (32, 16)
    flash_mma<<<fgrid, 256, FA_SMEM>>>(qh, kh, vh, yh);

    // output projection
    dim3 ogrid(DV / GBN, MROWS / GBM);         // (8, 32)
    mma_gemm<0><<<ogrid, 512, GEMM_SMEM>>>(yh, wh + 3 * (size_t)DV * DV,
                                           out, DV,
                                           nullptr, nullptr, nullptr, nullptr);
}